// round 14
// baseline (speedup 1.0000x reference)
#include <cuda_runtime.h>
#include <cuda_fp16.h>
#include <math.h>
#include <stdint.h>

#define B_SIZE  4
#define T_SEQ   2048
#define D_MODEL 1024
#define N_HEADS 16
#define H_DIM   64
#define M_ROWS  (B_SIZE * T_SEQ)   // 8192

// Scratch (no cudaMalloc allowed)
__device__ __half g_x_h[(size_t)M_ROWS * D_MODEL];
__device__ __half g_wqkv_t[(size_t)3 * D_MODEL * D_MODEL];  // [N=3072][K=1024]
__device__ __half g_wout_t[(size_t)D_MODEL * D_MODEL];      // [N=1024][K=1024]
__device__ __half g_qkv_h[(size_t)M_ROWS * 3 * D_MODEL];
__device__ __half g_att_h[(size_t)M_ROWS * D_MODEL];

__device__ __forceinline__ uint32_t smem_u32(const void* p) {
    uint32_t a;
    asm("{ .reg .u64 t; cvta.to.shared.u64 t, %1; cvt.u32.u64 %0, t; }" : "=r"(a) : "l"(p));
    return a;
}
__device__ __forceinline__ uint32_t packh2(float x, float y) {
    __half2 h = __floats2half2_rn(x, y);
    return *(uint32_t*)&h;
}

#define LDM_X4(r0, r1, r2, r3, addr)                                          \
    asm volatile("ldmatrix.sync.aligned.m8n8.x4.shared.b16 {%0,%1,%2,%3}, [%4];" \
        : "=r"(r0), "=r"(r1), "=r"(r2), "=r"(r3) : "r"(addr))
#define LDM_X4_T(r0, r1, r2, r3, addr)                                        \
    asm volatile("ldmatrix.sync.aligned.m8n8.x4.trans.shared.b16 {%0,%1,%2,%3}, [%4];" \
        : "=r"(r0), "=r"(r1), "=r"(r2), "=r"(r3) : "r"(addr))
#define MMA_F16(c, a, b)                                                      \
    asm volatile("mma.sync.aligned.m16n8k16.row.col.f32.f16.f16.f32 "         \
        "{%0,%1,%2,%3},{%4,%5,%6,%7},{%8,%9},{%0,%1,%2,%3};"                  \
        : "+f"((c)[0]), "+f"((c)[1]), "+f"((c)[2]), "+f"((c)[3])              \
        : "r"((a)[0]), "r"((a)[1]), "r"((a)[2]), "r"((a)[3]),                 \
          "r"((b)[0]), "r"((b)[1]))
#define CP_ASYNC16(dst, src) \
    asm volatile("cp.async.cg.shared.global [%0], [%1], 16;" :: "r"(dst), "l"(src))
#define CP_COMMIT() asm volatile("cp.async.commit_group;")
#define CP_WAIT1()  asm volatile("cp.async.wait_group 1;")
#define CP_WAIT0()  asm volatile("cp.async.wait_group 0;")

// ---------------------------------------------------------------------------
// Conversion pre-pass kernels
// ---------------------------------------------------------------------------
__global__ void conv_f16_kernel(const float* __restrict__ in, __half* __restrict__ outp, int n4)
{
    int i = blockIdx.x * blockDim.x + threadIdx.x;
    if (i >= n4) return;
    float4 v = ((const float4*)in)[i];
    __half2* o = (__half2*)outp + (size_t)i * 2;
    o[0] = __floats2half2_rn(v.x, v.y);
    o[1] = __floats2half2_rn(v.z, v.w);
}

// out[n][k] (f16) = in[k][n] (f32); R = rows(K) of in, C = cols(N) of in
__global__ void conv_transpose_f16(const float* __restrict__ in, __half* __restrict__ outp,
                                   int R, int C)
{
    __shared__ float t[32][33];
    int bx = blockIdx.x * 32, by = blockIdx.y * 32;
#pragma unroll
    for (int j = threadIdx.y; j < 32; j += 8)
        t[j][threadIdx.x] = in[(size_t)(by + j) * C + bx + threadIdx.x];
    __syncthreads();
#pragma unroll
    for (int j = threadIdx.y; j < 32; j += 8)
        outp[(size_t)(bx + j) * R + by + threadIdx.x] = __float2half_rn(t[threadIdx.x][j]);
}

// ---------------------------------------------------------------------------
// fp16 tensor-core GEMM: C[M,N] = A[M,K] * Bt[N,K]^T + bias[N]
// A, Bt: f16 K-major. 128x128 tile, BK=64 double-buffered cp.async.
// 8 warps (2x4), warp tile 64x32, m16n8k16. ldmatrix fragments. 2 CTAs/SM.
// Output: f32 (Cf) or f16 (Ch) selected by store_half.
// ---------------------------------------------------------------------------
#define GT   256
#define GBM  128
#define GBN  128
#define GBK  64
#define LDH  72                      // halves per smem row (144B, 16B-aligned, conflict-free)
#define GA_H (GBM * LDH)             // 9216 halves
#define GB_H (GBN * LDH)
#define G_SMEM_BYTES (2 * (GA_H + GB_H) * 2)   // 73728

__global__ void __launch_bounds__(GT, 2)
gemm_f16(int M, int N, int K,
         const __half* __restrict__ A,
         const __half* __restrict__ Bt,
         const float* __restrict__ bias,
         float* __restrict__ Cf, __half* __restrict__ Ch, int store_half)
{
    extern __shared__ __half gsm[];
    const uint32_t sA_u = smem_u32(gsm);
    const uint32_t sB_u = sA_u + 2 * GA_H * 2;   // after both A stages

    const int tid  = threadIdx.x;
    const int wid  = tid >> 5;
    const int lane = tid & 31;
    const int lq   = lane >> 2;
    const int lr   = lane & 3;
    const int wm   = wid & 1;
    const int wn   = wid >> 1;

    const size_t row0 = (size_t)blockIdx.y * GBM;
    const size_t col0 = (size_t)blockIdx.x * GBN;
    const int NC = K / GBK;

    const int lrow = tid >> 3;        // 0..31 (x4 via it)
    const int lch  = (tid & 7) * 8;   // half offset within row

    auto issue = [&](int kc, int buf) {
        const __half* Ag = A  + row0 * K + (size_t)kc * GBK;
        const __half* Bg = Bt + col0 * K + (size_t)kc * GBK;
        uint32_t dA = sA_u + (uint32_t)(buf * GA_H) * 2;
        uint32_t dB = sB_u + (uint32_t)(buf * GB_H) * 2;
#pragma unroll
        for (int it = 0; it < 4; ++it) {
            int r = lrow + it * 32;
            CP_ASYNC16(dA + (uint32_t)(r * LDH + lch) * 2, Ag + (size_t)r * K + lch);
            CP_ASYNC16(dB + (uint32_t)(r * LDH + lch) * 2, Bg + (size_t)r * K + lch);
        }
        CP_COMMIT();
    };

    float acc[4][4][4];
#pragma unroll
    for (int mi = 0; mi < 4; ++mi)
#pragma unroll
        for (int ni = 0; ni < 4; ++ni)
#pragma unroll
            for (int j = 0; j < 4; ++j) acc[mi][ni][j] = 0.0f;

    // ldmatrix lane address offsets (bytes) within a stage
    const uint32_t aOff = (uint32_t)((wm * 64 + (lane & 15)) * LDH + (lane >> 4) * 8) * 2;
    const uint32_t bOff = (uint32_t)((wn * 32 + (lane & 7) + ((lane >> 4) & 1) * 8) * LDH
                                     + ((lane >> 3) & 1) * 8) * 2;

    issue(0, 0);

    for (int kc = 0; kc < NC; ++kc) {
        if (kc + 1 < NC) { issue(kc + 1, (kc + 1) & 1); CP_WAIT1(); }
        else             { CP_WAIT0(); }
        __syncthreads();

        const uint32_t aS = sA_u + (uint32_t)((kc & 1) * GA_H) * 2 + aOff;
        const uint32_t bS = sB_u + (uint32_t)((kc & 1) * GB_H) * 2 + bOff;
#pragma unroll
        for (int kk = 0; kk < 4; ++kk) {
            uint32_t a[4][4], b[4][2];
#pragma unroll
            for (int mi = 0; mi < 4; ++mi)
                LDM_X4(a[mi][0], a[mi][1], a[mi][2], a[mi][3],
                       aS + (uint32_t)(mi * 16 * LDH) * 2 + kk * 32);
#pragma unroll
            for (int p = 0; p < 2; ++p)
                LDM_X4(b[2 * p][0], b[2 * p][1], b[2 * p + 1][0], b[2 * p + 1][1],
                       bS + (uint32_t)(p * 16 * LDH) * 2 + kk * 32);
#pragma unroll
            for (int mi = 0; mi < 4; ++mi)
#pragma unroll
                for (int ni = 0; ni < 4; ++ni)
                    MMA_F16(acc[mi][ni], a[mi], b[ni]);
        }
        __syncthreads();
    }

    // Epilogue
#pragma unroll
    for (int mi = 0; mi < 4; ++mi) {
#pragma unroll
        for (int ni = 0; ni < 4; ++ni) {
            size_t r  = row0 + wm * 64 + mi * 16 + lq;
            size_t cn = col0 + wn * 32 + ni * 8 + 2 * lr;
            float2 bv = *(const float2*)(bias + cn);
            float v00 = acc[mi][ni][0] + bv.x, v01 = acc[mi][ni][1] + bv.y;
            float v10 = acc[mi][ni][2] + bv.x, v11 = acc[mi][ni][3] + bv.y;
            if (store_half) {
                *(uint32_t*)(Ch + r * N + cn)       = packh2(v00, v01);
                *(uint32_t*)(Ch + (r + 8) * N + cn) = packh2(v10, v11);
            } else {
                *(float2*)(Cf + r * N + cn)       = make_float2(v00, v01);
                *(float2*)(Cf + (r + 8) * N + cn) = make_float2(v10, v11);
            }
        }
    }
}

// ---------------------------------------------------------------------------
// fp16 flash attention. 128 q-rows per CTA (8 warps x 16 rows), KV tiles of 64,
// double-buffered via cp.async. S C-frags repacked directly as PV A-frags.
// ---------------------------------------------------------------------------
#define AQ    128
#define AKV   64
#define AT_NT (T_SEQ / AKV)
#define Q_H   (AQ * LDH)             // 9216 halves
#define KV_H  (AKV * LDH)            // 4608 halves per stage
#define ATT_SMEM_BYTES ((Q_H + 4 * KV_H) * 2)   // 55296

__global__ void __launch_bounds__(256, 2)
flash_attn_f16(const __half* __restrict__ qkv, __half* __restrict__ outp)
{
    extern __shared__ __half hsm[];
    const uint32_t sQ_u = smem_u32(hsm);
    const uint32_t sK_u = sQ_u + Q_H * 2;            // 2 stages
    const uint32_t sV_u = sK_u + 2 * KV_H * 2;       // 2 stages

    const int tid  = threadIdx.x;
    const int wid  = tid >> 5;
    const int lane = tid & 31;
    const int lq   = lane >> 2;
    const int lr   = lane & 3;

    const int bh = blockIdx.y;
    const int b  = bh >> 4;
    const int h  = bh & 15;
    const int q0 = blockIdx.x * AQ;

    const __half* qb = qkv + ((size_t)b * T_SEQ) * (3 * D_MODEL) + h * H_DIM;
    const __half* kb = qb + D_MODEL;
    const __half* vb = qb + 2 * D_MODEL;

    const int lrow = tid >> 3;
    const int lch  = (tid & 7) * 8;

    // Q tile: 128 rows x 8 chunks
    {
#pragma unroll
        for (int it = 0; it < 4; ++it) {
            int r = lrow + it * 32;
            CP_ASYNC16(sQ_u + (uint32_t)(r * LDH + lch) * 2,
                       qb + (size_t)(q0 + r) * (3 * D_MODEL) + lch);
        }
    }
    auto issue_kv = [&](int kt, int buf) {
        int k0 = kt * AKV;
        uint32_t dK = sK_u + (uint32_t)(buf * KV_H) * 2;
        uint32_t dV = sV_u + (uint32_t)(buf * KV_H) * 2;
#pragma unroll
        for (int it = 0; it < 2; ++it) {
            int r = lrow + it * 32;
            CP_ASYNC16(dK + (uint32_t)(r * LDH + lch) * 2,
                       kb + (size_t)(k0 + r) * (3 * D_MODEL) + lch);
            CP_ASYNC16(dV + (uint32_t)(r * LDH + lch) * 2,
                       vb + (size_t)(k0 + r) * (3 * D_MODEL) + lch);
        }
    };
    issue_kv(0, 0);
    CP_COMMIT();            // G0: Q + KV0
    issue_kv(1, 1);
    CP_COMMIT();            // G1: KV1

    float o[8][4];
    float m0 = -INFINITY, m1 = -INFINITY, l0 = 0.0f, l1 = 0.0f;
#pragma unroll
    for (int ni = 0; ni < 8; ++ni)
#pragma unroll
        for (int j = 0; j < 4; ++j) o[ni][j] = 0.0f;

    const float scale = 0.125f;
    uint32_t qfrag[4][4];

    // ldmatrix lane offsets (bytes)
    const uint32_t qOff = (uint32_t)((wid * 16 + (lane & 15)) * LDH + (lane >> 4) * 8) * 2;
    const uint32_t kOff = (uint32_t)(((lane & 7) + ((lane >> 4) & 1) * 8) * LDH
                                     + ((lane >> 3) & 1) * 8) * 2;
    const uint32_t vOff = (uint32_t)(((lane & 7) + ((lane >> 3) & 1) * 8) * LDH
                                     + (lane >> 4) * 8) * 2;

    for (int kt = 0; kt < AT_NT; ++kt) {
        if (kt + 1 < AT_NT) CP_WAIT1(); else CP_WAIT0();
        __syncthreads();

        if (kt == 0) {
#pragma unroll
            for (int kk = 0; kk < 4; ++kk)
                LDM_X4(qfrag[kk][0], qfrag[kk][1], qfrag[kk][2], qfrag[kk][3],
                       sQ_u + qOff + kk * 32);
        }

        const uint32_t kS = sK_u + (uint32_t)((kt & 1) * KV_H) * 2 + kOff;
        const uint32_t vS = sV_u + (uint32_t)((kt & 1) * KV_H) * 2 + vOff;

        // S = Q K^T  (16 x 64 per warp)
        float c[8][4];
#pragma unroll
        for (int ni = 0; ni < 8; ++ni)
#pragma unroll
            for (int j = 0; j < 4; ++j) c[ni][j] = 0.0f;

#pragma unroll
        for (int kk = 0; kk < 4; ++kk) {
            uint32_t bfr[8][2];
#pragma unroll
            for (int p = 0; p < 4; ++p)
                LDM_X4(bfr[2 * p][0], bfr[2 * p][1], bfr[2 * p + 1][0], bfr[2 * p + 1][1],
                       kS + (uint32_t)(p * 16 * LDH) * 2 + kk * 32);
#pragma unroll
            for (int ni = 0; ni < 8; ++ni)
                MMA_F16(c[ni], qfrag[kk], bfr[ni]);
        }

        // Online softmax (rows lq via c[.][0,1], lq+8 via c[.][2,3])
        float rm0 = -INFINITY, rm1 = -INFINITY;
#pragma unroll
        for (int ni = 0; ni < 8; ++ni) {
#pragma unroll
            for (int j = 0; j < 4; ++j) c[ni][j] *= scale;
            rm0 = fmaxf(rm0, fmaxf(c[ni][0], c[ni][1]));
            rm1 = fmaxf(rm1, fmaxf(c[ni][2], c[ni][3]));
        }
        rm0 = fmaxf(rm0, __shfl_xor_sync(0xffffffffu, rm0, 1));
        rm0 = fmaxf(rm0, __shfl_xor_sync(0xffffffffu, rm0, 2));
        rm1 = fmaxf(rm1, __shfl_xor_sync(0xffffffffu, rm1, 1));
        rm1 = fmaxf(rm1, __shfl_xor_sync(0xffffffffu, rm1, 2));

        float mn0 = fmaxf(m0, rm0), mn1 = fmaxf(m1, rm1);
        float al0 = __expf(m0 - mn0), al1 = __expf(m1 - mn1);
        m0 = mn0; m1 = mn1;

        float rs0 = 0.0f, rs1 = 0.0f;
#pragma unroll
        for (int ni = 0; ni < 8; ++ni) {
            c[ni][0] = __expf(c[ni][0] - mn0);
            c[ni][1] = __expf(c[ni][1] - mn0);
            c[ni][2] = __expf(c[ni][2] - mn1);
            c[ni][3] = __expf(c[ni][3] - mn1);
            rs0 += c[ni][0] + c[ni][1];
            rs1 += c[ni][2] + c[ni][3];
        }
        rs0 += __shfl_xor_sync(0xffffffffu, rs0, 1);
        rs0 += __shfl_xor_sync(0xffffffffu, rs0, 2);
        rs1 += __shfl_xor_sync(0xffffffffu, rs1, 1);
        rs1 += __shfl_xor_sync(0xffffffffu, rs1, 2);

        l0 = l0 * al0 + rs0;
        l1 = l1 * al1 + rs1;
#pragma unroll
        for (int ni = 0; ni < 8; ++ni) {
            o[ni][0] *= al0; o[ni][1] *= al0;
            o[ni][2] *= al1; o[ni][3] *= al1;
        }

        // O += P @ V : P fragments packed directly from S C-frags
#pragma unroll
        for (int j = 0; j < 4; ++j) {
            uint32_t a[4];
            a[0] = packh2(c[2 * j][0],     c[2 * j][1]);
            a[1] = packh2(c[2 * j][2],     c[2 * j][3]);
            a[2] = packh2(c[2 * j + 1][0], c[2 * j + 1][1]);
            a[3] = packh2(c[2 * j + 1][2], c[2 * j + 1][3]);
            uint32_t bfr[8][2];
#pragma unroll
            for (int p = 0; p < 4; ++p)
                LDM_X4_T(bfr[2 * p][0], bfr[2 * p][1], bfr[2 * p + 1][0], bfr[2 * p + 1][1],
                         vS + (uint32_t)(j * 16 * LDH) * 2 + p * 32);
#pragma unroll
            for (int ni = 0; ni < 8; ++ni)
                MMA_F16(o[ni], a, bfr[ni]);
        }

        __syncthreads();
        if (kt + 2 < AT_NT) { issue_kv(kt + 2, kt & 1); CP_COMMIT(); }
    }

    // Normalize + write f16
    float inv0 = 1.0f / l0, inv1 = 1.0f / l1;
    size_t row_g = (size_t)b * T_SEQ + q0 + wid * 16 + lq;
#pragma unroll
    for (int ni = 0; ni < 8; ++ni) {
        int cn = h * H_DIM + ni * 8 + 2 * lr;
        *(uint32_t*)(outp + row_g * D_MODEL + cn) =
            packh2(o[ni][0] * inv0, o[ni][1] * inv0);
        *(uint32_t*)(outp + (row_g + 8) * D_MODEL + cn) =
            packh2(o[ni][2] * inv1, o[ni][3] * inv1);
    }
}

// ---------------------------------------------------------------------------
extern "C" void kernel_launch(void* const* d_in, const int* in_sizes, int n_in,
                              void* d_out, int out_size)
{
    const float* x     = (const float*)d_in[0];
    const float* W_qkv = (const float*)d_in[1];
    const float* b_qkv = (const float*)d_in[2];
    const float* W_out = (const float*)d_in[3];
    const float* b_out = (const float*)d_in[4];
    float*       out   = (float*)d_out;

    __half *x_h, *wqkv_t, *wout_t, *qkv_h, *att_h;
    cudaGetSymbolAddress((void**)&x_h,    g_x_h);
    cudaGetSymbolAddress((void**)&wqkv_t, g_wqkv_t);
    cudaGetSymbolAddress((void**)&wout_t, g_wout_t);
    cudaGetSymbolAddress((void**)&qkv_h,  g_qkv_h);
    cudaGetSymbolAddress((void**)&att_h,  g_att_h);

    cudaFuncSetAttribute(gemm_f16,
                         cudaFuncAttributeMaxDynamicSharedMemorySize, G_SMEM_BYTES);
    cudaFuncSetAttribute(flash_attn_f16,
                         cudaFuncAttributeMaxDynamicSharedMemorySize, ATT_SMEM_BYTES);

    // 0) Conversions: x -> f16; W -> W^T f16
    {
        int n4 = (M_ROWS * D_MODEL) / 4;
        conv_f16_kernel<<<(n4 + 255) / 256, 256>>>(x, x_h, n4);
        dim3 blk(32, 8);
        conv_transpose_f16<<<dim3((3 * D_MODEL) / 32, D_MODEL / 32), blk>>>(
            W_qkv, wqkv_t, D_MODEL, 3 * D_MODEL);
        conv_transpose_f16<<<dim3(D_MODEL / 32, D_MODEL / 32), blk>>>(
            W_out, wout_t, D_MODEL, D_MODEL);
    }

    // 1) QKV projection -> f16 qkv
    {
        dim3 grid((3 * D_MODEL) / GBN, M_ROWS / GBM);
        gemm_f16<<<grid, GT, G_SMEM_BYTES>>>(
            M_ROWS, 3 * D_MODEL, D_MODEL, x_h, wqkv_t, b_qkv, nullptr, qkv_h, 1);
    }

    // 2) Attention -> f16 att
    {
        dim3 grid(T_SEQ / AQ, B_SIZE * N_HEADS);
        flash_attn_f16<<<grid, 256, ATT_SMEM_BYTES>>>(qkv_h, att_h);
    }

    // 3) Output projection -> f32 out
    {
        dim3 grid(D_MODEL / GBN, M_ROWS / GBM);
        gemm_f16<<<grid, GT, G_SMEM_BYTES>>>(
            M_ROWS, D_MODEL, D_MODEL, att_h, wout_t, b_out, out, nullptr, 0);
    }
}

// round 15
// speedup vs baseline: 1.0009x; 1.0009x over previous
#include <cuda_runtime.h>
#include <cuda_fp16.h>
#include <math.h>
#include <stdint.h>

#define B_SIZE  4
#define T_SEQ   2048
#define D_MODEL 1024
#define N_HEADS 16
#define H_DIM   64
#define M_ROWS  (B_SIZE * T_SEQ)   // 8192

// Scratch (no cudaMalloc allowed)
__device__ __half g_x_h[(size_t)M_ROWS * D_MODEL];
__device__ __half g_wqkv_t[(size_t)3 * D_MODEL * D_MODEL];  // [N=3072][K=1024]
__device__ __half g_wout_t[(size_t)D_MODEL * D_MODEL];      // [N=1024][K=1024]
__device__ __half g_qkv_h[(size_t)M_ROWS * 3 * D_MODEL];
__device__ __half g_att_h[(size_t)M_ROWS * D_MODEL];

__device__ __forceinline__ uint32_t smem_u32(const void* p) {
    uint32_t a;
    asm("{ .reg .u64 t; cvta.to.shared.u64 t, %1; cvt.u32.u64 %0, t; }" : "=r"(a) : "l"(p));
    return a;
}
__device__ __forceinline__ uint32_t packh2(float x, float y) {
    __half2 h = __floats2half2_rn(x, y);
    return *(uint32_t*)&h;
}

#define LDM_X4(r0, r1, r2, r3, addr)                                          \
    asm volatile("ldmatrix.sync.aligned.m8n8.x4.shared.b16 {%0,%1,%2,%3}, [%4];" \
        : "=r"(r0), "=r"(r1), "=r"(r2), "=r"(r3) : "r"(addr))
#define LDM_X4_T(r0, r1, r2, r3, addr)                                        \
    asm volatile("ldmatrix.sync.aligned.m8n8.x4.trans.shared.b16 {%0,%1,%2,%3}, [%4];" \
        : "=r"(r0), "=r"(r1), "=r"(r2), "=r"(r3) : "r"(addr))
#define MMA_F16(c, a, b)                                                      \
    asm volatile("mma.sync.aligned.m16n8k16.row.col.f32.f16.f16.f32 "         \
        "{%0,%1,%2,%3},{%4,%5,%6,%7},{%8,%9},{%0,%1,%2,%3};"                  \
        : "+f"((c)[0]), "+f"((c)[1]), "+f"((c)[2]), "+f"((c)[3])              \
        : "r"((a)[0]), "r"((a)[1]), "r"((a)[2]), "r"((a)[3]),                 \
          "r"((b)[0]), "r"((b)[1]))
#define CP_ASYNC16(dst, src) \
    asm volatile("cp.async.cg.shared.global [%0], [%1], 16;" :: "r"(dst), "l"(src))
#define CP_COMMIT() asm volatile("cp.async.commit_group;")
#define CP_WAIT1()  asm volatile("cp.async.wait_group 1;")
#define CP_WAIT0()  asm volatile("cp.async.wait_group 0;")

// ---------------------------------------------------------------------------
// Conversion pre-pass kernels
// ---------------------------------------------------------------------------
__global__ void conv_f16_kernel(const float* __restrict__ in, __half* __restrict__ outp, int n4)
{
    int i = blockIdx.x * blockDim.x + threadIdx.x;
    if (i >= n4) return;
    float4 v = ((const float4*)in)[i];
    __half2* o = (__half2*)outp + (size_t)i * 2;
    o[0] = __floats2half2_rn(v.x, v.y);
    o[1] = __floats2half2_rn(v.z, v.w);
}

// out[n][k] (f16) = in[k][n] (f32); R = rows(K) of in, C = cols(N) of in
__global__ void conv_transpose_f16(const float* __restrict__ in, __half* __restrict__ outp,
                                   int R, int C)
{
    __shared__ float t[32][33];
    int bx = blockIdx.x * 32, by = blockIdx.y * 32;
#pragma unroll
    for (int j = threadIdx.y; j < 32; j += 8)
        t[j][threadIdx.x] = in[(size_t)(by + j) * C + bx + threadIdx.x];
    __syncthreads();
#pragma unroll
    for (int j = threadIdx.y; j < 32; j += 8)
        outp[(size_t)(bx + j) * R + by + threadIdx.x] = __float2half_rn(t[threadIdx.x][j]);
}

// ---------------------------------------------------------------------------
// fp16 tensor-core GEMM: C[M,N] = A[M,K] * Bt[N,K]^T + bias[N]
// A, Bt: f16 K-major. 128x128 tile, BK=64 double-buffered cp.async.
// 8 warps (2x4), warp tile 64x32, m16n8k16. ldmatrix fragments. 2 CTAs/SM.
// Output: f32 (Cf) or f16 (Ch) selected by store_half.
// ---------------------------------------------------------------------------
#define GT   256
#define GBM  128
#define GBN  128
#define GBK  64
#define LDH  72                      // halves per smem row (144B, 16B-aligned, conflict-free)
#define GA_H (GBM * LDH)             // 9216 halves
#define GB_H (GBN * LDH)
#define G_SMEM_BYTES (2 * (GA_H + GB_H) * 2)   // 73728

__global__ void __launch_bounds__(GT, 2)
gemm_f16(int M, int N, int K,
         const __half* __restrict__ A,
         const __half* __restrict__ Bt,
         const float* __restrict__ bias,
         float* __restrict__ Cf, __half* __restrict__ Ch, int store_half)
{
    extern __shared__ __half gsm[];
    const uint32_t sA_u = smem_u32(gsm);
    const uint32_t sB_u = sA_u + 2 * GA_H * 2;   // after both A stages

    const int tid  = threadIdx.x;
    const int wid  = tid >> 5;
    const int lane = tid & 31;
    const int lq   = lane >> 2;
    const int lr   = lane & 3;
    const int wm   = wid & 1;
    const int wn   = wid >> 1;

    const size_t row0 = (size_t)blockIdx.y * GBM;
    const size_t col0 = (size_t)blockIdx.x * GBN;
    const int NC = K / GBK;

    const int lrow = tid >> 3;        // 0..31 (x4 via it)
    const int lch  = (tid & 7) * 8;   // half offset within row

    auto issue = [&](int kc, int buf) {
        const __half* Ag = A  + row0 * K + (size_t)kc * GBK;
        const __half* Bg = Bt + col0 * K + (size_t)kc * GBK;
        uint32_t dA = sA_u + (uint32_t)(buf * GA_H) * 2;
        uint32_t dB = sB_u + (uint32_t)(buf * GB_H) * 2;
#pragma unroll
        for (int it = 0; it < 4; ++it) {
            int r = lrow + it * 32;
            CP_ASYNC16(dA + (uint32_t)(r * LDH + lch) * 2, Ag + (size_t)r * K + lch);
            CP_ASYNC16(dB + (uint32_t)(r * LDH + lch) * 2, Bg + (size_t)r * K + lch);
        }
        CP_COMMIT();
    };

    float acc[4][4][4];
#pragma unroll
    for (int mi = 0; mi < 4; ++mi)
#pragma unroll
        for (int ni = 0; ni < 4; ++ni)
#pragma unroll
            for (int j = 0; j < 4; ++j) acc[mi][ni][j] = 0.0f;

    // ldmatrix lane address offsets (bytes) within a stage
    const uint32_t aOff = (uint32_t)((wm * 64 + (lane & 15)) * LDH + (lane >> 4) * 8) * 2;
    const uint32_t bOff = (uint32_t)((wn * 32 + (lane & 7) + ((lane >> 4) & 1) * 8) * LDH
                                     + ((lane >> 3) & 1) * 8) * 2;

    issue(0, 0);

    for (int kc = 0; kc < NC; ++kc) {
        if (kc + 1 < NC) { issue(kc + 1, (kc + 1) & 1); CP_WAIT1(); }
        else             { CP_WAIT0(); }
        __syncthreads();

        const uint32_t aS = sA_u + (uint32_t)((kc & 1) * GA_H) * 2 + aOff;
        const uint32_t bS = sB_u + (uint32_t)((kc & 1) * GB_H) * 2 + bOff;
#pragma unroll
        for (int kk = 0; kk < 4; ++kk) {
            uint32_t a[4][4], b[4][2];
#pragma unroll
            for (int mi = 0; mi < 4; ++mi)
                LDM_X4(a[mi][0], a[mi][1], a[mi][2], a[mi][3],
                       aS + (uint32_t)(mi * 16 * LDH) * 2 + kk * 32);
#pragma unroll
            for (int p = 0; p < 2; ++p)
                LDM_X4(b[2 * p][0], b[2 * p][1], b[2 * p + 1][0], b[2 * p + 1][1],
                       bS + (uint32_t)(p * 16 * LDH) * 2 + kk * 32);
#pragma unroll
            for (int mi = 0; mi < 4; ++mi)
#pragma unroll
                for (int ni = 0; ni < 4; ++ni)
                    MMA_F16(acc[mi][ni], a[mi], b[ni]);
        }
        __syncthreads();
    }

    // Epilogue
#pragma unroll
    for (int mi = 0; mi < 4; ++mi) {
#pragma unroll
        for (int ni = 0; ni < 4; ++ni) {
            size_t r  = row0 + wm * 64 + mi * 16 + lq;
            size_t cn = col0 + wn * 32 + ni * 8 + 2 * lr;
            float2 bv = *(const float2*)(bias + cn);
            float v00 = acc[mi][ni][0] + bv.x, v01 = acc[mi][ni][1] + bv.y;
            float v10 = acc[mi][ni][2] + bv.x, v11 = acc[mi][ni][3] + bv.y;
            if (store_half) {
                *(uint32_t*)(Ch + r * N + cn)       = packh2(v00, v01);
                *(uint32_t*)(Ch + (r + 8) * N + cn) = packh2(v10, v11);
            } else {
                *(float2*)(Cf + r * N + cn)       = make_float2(v00, v01);
                *(float2*)(Cf + (r + 8) * N + cn) = make_float2(v10, v11);
            }
        }
    }
}

// ---------------------------------------------------------------------------
// fp16 flash attention. 128 q-rows per CTA (8 warps x 16 rows), KV tiles of 64,
// double-buffered via cp.async. S C-frags repacked directly as PV A-frags.
// ---------------------------------------------------------------------------
#define AQ    128
#define AKV   64
#define AT_NT (T_SEQ / AKV)
#define Q_H   (AQ * LDH)             // 9216 halves
#define KV_H  (AKV * LDH)            // 4608 halves per stage
#define ATT_SMEM_BYTES ((Q_H + 4 * KV_H) * 2)   // 55296

__global__ void __launch_bounds__(256, 2)
flash_attn_f16(const __half* __restrict__ qkv, __half* __restrict__ outp)
{
    extern __shared__ __half hsm[];
    const uint32_t sQ_u = smem_u32(hsm);
    const uint32_t sK_u = sQ_u + Q_H * 2;            // 2 stages
    const uint32_t sV_u = sK_u + 2 * KV_H * 2;       // 2 stages

    const int tid  = threadIdx.x;
    const int wid  = tid >> 5;
    const int lane = tid & 31;
    const int lq   = lane >> 2;
    const int lr   = lane & 3;

    const int bh = blockIdx.y;
    const int b  = bh >> 4;
    const int h  = bh & 15;
    const int q0 = blockIdx.x * AQ;

    const __half* qb = qkv + ((size_t)b * T_SEQ) * (3 * D_MODEL) + h * H_DIM;
    const __half* kb = qb + D_MODEL;
    const __half* vb = qb + 2 * D_MODEL;

    const int lrow = tid >> 3;
    const int lch  = (tid & 7) * 8;

    // Q tile: 128 rows x 8 chunks
    {
#pragma unroll
        for (int it = 0; it < 4; ++it) {
            int r = lrow + it * 32;
            CP_ASYNC16(sQ_u + (uint32_t)(r * LDH + lch) * 2,
                       qb + (size_t)(q0 + r) * (3 * D_MODEL) + lch);
        }
    }
    auto issue_kv = [&](int kt, int buf) {
        int k0 = kt * AKV;
        uint32_t dK = sK_u + (uint32_t)(buf * KV_H) * 2;
        uint32_t dV = sV_u + (uint32_t)(buf * KV_H) * 2;
#pragma unroll
        for (int it = 0; it < 2; ++it) {
            int r = lrow + it * 32;
            CP_ASYNC16(dK + (uint32_t)(r * LDH + lch) * 2,
                       kb + (size_t)(k0 + r) * (3 * D_MODEL) + lch);
            CP_ASYNC16(dV + (uint32_t)(r * LDH + lch) * 2,
                       vb + (size_t)(k0 + r) * (3 * D_MODEL) + lch);
        }
    };
    issue_kv(0, 0);
    CP_COMMIT();            // G0: Q + KV0
    issue_kv(1, 1);
    CP_COMMIT();            // G1: KV1

    float o[8][4];
    float m0 = -INFINITY, m1 = -INFINITY, l0 = 0.0f, l1 = 0.0f;
#pragma unroll
    for (int ni = 0; ni < 8; ++ni)
#pragma unroll
        for (int j = 0; j < 4; ++j) o[ni][j] = 0.0f;

    const float scale = 0.125f;
    uint32_t qfrag[4][4];

    // ldmatrix lane offsets (bytes)
    const uint32_t qOff = (uint32_t)((wid * 16 + (lane & 15)) * LDH + (lane >> 4) * 8) * 2;
    const uint32_t kOff = (uint32_t)(((lane & 7) + ((lane >> 4) & 1) * 8) * LDH
                                     + ((lane >> 3) & 1) * 8) * 2;
    const uint32_t vOff = (uint32_t)(((lane & 7) + ((lane >> 3) & 1) * 8) * LDH
                                     + (lane >> 4) * 8) * 2;

    for (int kt = 0; kt < AT_NT; ++kt) {
        if (kt + 1 < AT_NT) CP_WAIT1(); else CP_WAIT0();
        __syncthreads();

        if (kt == 0) {
#pragma unroll
            for (int kk = 0; kk < 4; ++kk)
                LDM_X4(qfrag[kk][0], qfrag[kk][1], qfrag[kk][2], qfrag[kk][3],
                       sQ_u + qOff + kk * 32);
        }

        const uint32_t kS = sK_u + (uint32_t)((kt & 1) * KV_H) * 2 + kOff;
        const uint32_t vS = sV_u + (uint32_t)((kt & 1) * KV_H) * 2 + vOff;

        // S = Q K^T  (16 x 64 per warp)
        float c[8][4];
#pragma unroll
        for (int ni = 0; ni < 8; ++ni)
#pragma unroll
            for (int j = 0; j < 4; ++j) c[ni][j] = 0.0f;

#pragma unroll
        for (int kk = 0; kk < 4; ++kk) {
            uint32_t bfr[8][2];
#pragma unroll
            for (int p = 0; p < 4; ++p)
                LDM_X4(bfr[2 * p][0], bfr[2 * p][1], bfr[2 * p + 1][0], bfr[2 * p + 1][1],
                       kS + (uint32_t)(p * 16 * LDH) * 2 + kk * 32);
#pragma unroll
            for (int ni = 0; ni < 8; ++ni)
                MMA_F16(c[ni], qfrag[kk], bfr[ni]);
        }

        // Online softmax (rows lq via c[.][0,1], lq+8 via c[.][2,3])
        float rm0 = -INFINITY, rm1 = -INFINITY;
#pragma unroll
        for (int ni = 0; ni < 8; ++ni) {
#pragma unroll
            for (int j = 0; j < 4; ++j) c[ni][j] *= scale;
            rm0 = fmaxf(rm0, fmaxf(c[ni][0], c[ni][1]));
            rm1 = fmaxf(rm1, fmaxf(c[ni][2], c[ni][3]));
        }
        rm0 = fmaxf(rm0, __shfl_xor_sync(0xffffffffu, rm0, 1));
        rm0 = fmaxf(rm0, __shfl_xor_sync(0xffffffffu, rm0, 2));
        rm1 = fmaxf(rm1, __shfl_xor_sync(0xffffffffu, rm1, 1));
        rm1 = fmaxf(rm1, __shfl_xor_sync(0xffffffffu, rm1, 2));

        float mn0 = fmaxf(m0, rm0), mn1 = fmaxf(m1, rm1);
        float al0 = __expf(m0 - mn0), al1 = __expf(m1 - mn1);
        m0 = mn0; m1 = mn1;

        float rs0 = 0.0f, rs1 = 0.0f;
#pragma unroll
        for (int ni = 0; ni < 8; ++ni) {
            c[ni][0] = __expf(c[ni][0] - mn0);
            c[ni][1] = __expf(c[ni][1] - mn0);
            c[ni][2] = __expf(c[ni][2] - mn1);
            c[ni][3] = __expf(c[ni][3] - mn1);
            rs0 += c[ni][0] + c[ni][1];
            rs1 += c[ni][2] + c[ni][3];
        }
        rs0 += __shfl_xor_sync(0xffffffffu, rs0, 1);
        rs0 += __shfl_xor_sync(0xffffffffu, rs0, 2);
        rs1 += __shfl_xor_sync(0xffffffffu, rs1, 1);
        rs1 += __shfl_xor_sync(0xffffffffu, rs1, 2);

        l0 = l0 * al0 + rs0;
        l1 = l1 * al1 + rs1;
#pragma unroll
        for (int ni = 0; ni < 8; ++ni) {
            o[ni][0] *= al0; o[ni][1] *= al0;
            o[ni][2] *= al1; o[ni][3] *= al1;
        }

        // O += P @ V : P fragments packed directly from S C-frags
#pragma unroll
        for (int j = 0; j < 4; ++j) {
            uint32_t a[4];
            a[0] = packh2(c[2 * j][0],     c[2 * j][1]);
            a[1] = packh2(c[2 * j][2],     c[2 * j][3]);
            a[2] = packh2(c[2 * j + 1][0], c[2 * j + 1][1]);
            a[3] = packh2(c[2 * j + 1][2], c[2 * j + 1][3]);
            uint32_t bfr[8][2];
#pragma unroll
            for (int p = 0; p < 4; ++p)
                LDM_X4_T(bfr[2 * p][0], bfr[2 * p][1], bfr[2 * p + 1][0], bfr[2 * p + 1][1],
                         vS + (uint32_t)(j * 16 * LDH) * 2 + p * 32);
#pragma unroll
            for (int ni = 0; ni < 8; ++ni)
                MMA_F16(o[ni], a, bfr[ni]);
        }

        __syncthreads();
        if (kt + 2 < AT_NT) { issue_kv(kt + 2, kt & 1); CP_COMMIT(); }
    }

    // Normalize + write f16
    float inv0 = 1.0f / l0, inv1 = 1.0f / l1;
    size_t row_g = (size_t)b * T_SEQ + q0 + wid * 16 + lq;
#pragma unroll
    for (int ni = 0; ni < 8; ++ni) {
        int cn = h * H_DIM + ni * 8 + 2 * lr;
        *(uint32_t*)(outp + row_g * D_MODEL + cn) =
            packh2(o[ni][0] * inv0, o[ni][1] * inv0);
        *(uint32_t*)(outp + (row_g + 8) * D_MODEL + cn) =
            packh2(o[ni][2] * inv1, o[ni][3] * inv1);
    }
}

// ---------------------------------------------------------------------------
extern "C" void kernel_launch(void* const* d_in, const int* in_sizes, int n_in,
                              void* d_out, int out_size)
{
    const float* x     = (const float*)d_in[0];
    const float* W_qkv = (const float*)d_in[1];
    const float* b_qkv = (const float*)d_in[2];
    const float* W_out = (const float*)d_in[3];
    const float* b_out = (const float*)d_in[4];
    float*       out   = (float*)d_out;

    __half *x_h, *wqkv_t, *wout_t, *qkv_h, *att_h;
    cudaGetSymbolAddress((void**)&x_h,    g_x_h);
    cudaGetSymbolAddress((void**)&wqkv_t, g_wqkv_t);
    cudaGetSymbolAddress((void**)&wout_t, g_wout_t);
    cudaGetSymbolAddress((void**)&qkv_h,  g_qkv_h);
    cudaGetSymbolAddress((void**)&att_h,  g_att_h);

    cudaFuncSetAttribute(gemm_f16,
                         cudaFuncAttributeMaxDynamicSharedMemorySize, G_SMEM_BYTES);
    cudaFuncSetAttribute(flash_attn_f16,
                         cudaFuncAttributeMaxDynamicSharedMemorySize, ATT_SMEM_BYTES);

    // 0) Conversions: x -> f16; W -> W^T f16
    {
        int n4 = (M_ROWS * D_MODEL) / 4;
        conv_f16_kernel<<<(n4 + 255) / 256, 256>>>(x, x_h, n4);
        dim3 blk(32, 8);
        conv_transpose_f16<<<dim3((3 * D_MODEL) / 32, D_MODEL / 32), blk>>>(
            W_qkv, wqkv_t, D_MODEL, 3 * D_MODEL);
        conv_transpose_f16<<<dim3(D_MODEL / 32, D_MODEL / 32), blk>>>(
            W_out, wout_t, D_MODEL, D_MODEL);
    }

    // 1) QKV projection -> f16 qkv
    {
        dim3 grid((3 * D_MODEL) / GBN, M_ROWS / GBM);
        gemm_f16<<<grid, GT, G_SMEM_BYTES>>>(
            M_ROWS, 3 * D_MODEL, D_MODEL, x_h, wqkv_t, b_qkv, nullptr, qkv_h, 1);
    }

    // 2) Attention -> f16 att
    {
        dim3 grid(T_SEQ / AQ, B_SIZE * N_HEADS);
        flash_attn_f16<<<grid, 256, ATT_SMEM_BYTES>>>(qkv_h, att_h);
    }

    // 3) Output projection -> f32 out
    {
        dim3 grid(D_MODEL / GBN, M_ROWS / GBM);
        gemm_f16<<<grid, GT, G_SMEM_BYTES>>>(
            M_ROWS, D_MODEL, D_MODEL, att_h, wout_t, b_out, out, nullptr, 0);
    }
}